// round 1
// baseline (speedup 1.0000x reference)
#include <cuda_runtime.h>
#include <float.h>
#include <math.h>

#define NPTS 4096
#define NB 2
#define NN 8192
#define DD 64
#define KK 5
#define NKB (NPTS*KK)      /* 20480 flat (k-major) per batch */
#define EDGES (NB*NKB)     /* 40960 edges */

/* ---------------- scratch (device globals; no allocation allowed) -------- */
__device__ float    g_xf1[NN*DD];
__device__ float    g_ge1[NN*DD];
__device__ float    g_ge2[NN*DD];
__device__ float    g_sq [NN];
__device__ int      g_idx1[NB*NKB];
__device__ int      g_idx2[NB*NKB];
__device__ float    g_A  [NN*DD];
__device__ float    g_B  [NN*DD];
__device__ unsigned g_acc[NN*DD];
__device__ float    g_x2 [NN*DD];
__device__ float    g_x3 [NN*DD];
__device__ float    g_Wdiff[DD*DD];

/* ordered float<->uint key (monotone map, finite floats) */
__device__ __forceinline__ unsigned fkey(float f) {
    unsigned u = __float_as_uint(f);
    return u ^ ((unsigned)(((int)u) >> 31) | 0x80000000u);
}
__device__ __forceinline__ float fdec(unsigned u) {
    unsigned v = u ^ ((u & 0x80000000u) ? 0x80000000u : 0xFFFFFFFFu);
    return __uint_as_float(v);
}
#define NEG_MAX_KEY 0x00800000u   /* fkey(-FLT_MAX) */

/* ---------------- generic small GEMM: Y = act(X@W + b), 64 rows/block ---- */
template<int NCOL>
__global__ __launch_bounds__(256) void gemm_act(
    const float* __restrict__ X1, int k1,
    const float* __restrict__ X2, int k2,
    const float* __restrict__ W, const float* __restrict__ bias,
    float* __restrict__ Y, int act)
{
    constexpr int G  = NCOL / 4;
    constexpr int TY = 256 / G;
    constexpr int R  = 64 / TY;
    __shared__ float Ws[128 * NCOL];
    __shared__ float Xs[64 * 33];
    __shared__ float bs[NCOL];
    const int t = threadIdx.x;
    const int rowBase = blockIdx.x * 64;
    const int KD = k1 + k2;

    for (int f = t; f < KD * NCOL; f += 256) Ws[f] = W[f];
    if (t < NCOL) bs[t] = (bias != nullptr) ? bias[t] : 0.0f;

    const int tx = t % G, ty = t / G;
    float acc[R][4];
#pragma unroll
    for (int rr = 0; rr < R; rr++) { acc[rr][0]=0.f; acc[rr][1]=0.f; acc[rr][2]=0.f; acc[rr][3]=0.f; }

    for (int ko = 0; ko < KD; ko += 32) {
        const float* Xsrc; int stride, koff;
        if (ko < k1) { Xsrc = X1; stride = k1; koff = ko; }
        else         { Xsrc = X2; stride = k2; koff = ko - k1; }
        __syncthreads();
        for (int f = t; f < 64 * 32; f += 256) {
            int r = f >> 5, k = f & 31;
            Xs[r * 33 + k] = Xsrc[(rowBase + r) * stride + koff + k];
        }
        __syncthreads();
#pragma unroll
        for (int k = 0; k < 32; k++) {
            float4 w4 = *(const float4*)(Ws + (ko + k) * NCOL + tx * 4);
#pragma unroll
            for (int rr = 0; rr < R; rr++) {
                float xv = Xs[(ty + rr * TY) * 33 + k];
                acc[rr][0] += xv * w4.x; acc[rr][1] += xv * w4.y;
                acc[rr][2] += xv * w4.z; acc[rr][3] += xv * w4.w;
            }
        }
    }
#pragma unroll
    for (int rr = 0; rr < R; rr++) {
        int r = rowBase + ty + rr * TY;
        float4 o;
        o.x = acc[rr][0] + bs[tx*4+0];
        o.y = acc[rr][1] + bs[tx*4+1];
        o.z = acc[rr][2] + bs[tx*4+2];
        o.w = acc[rr][3] + bs[tx*4+3];
        if (act == 1) {          /* leaky relu 0.1 */
            o.x = o.x > 0.f ? o.x : 0.1f*o.x; o.y = o.y > 0.f ? o.y : 0.1f*o.y;
            o.z = o.z > 0.f ? o.z : 0.1f*o.z; o.w = o.w > 0.f ? o.w : 0.1f*o.w;
        } else if (act == 2) {   /* relu */
            o.x = fmaxf(o.x,0.f); o.y = fmaxf(o.y,0.f);
            o.z = fmaxf(o.z,0.f); o.w = fmaxf(o.w,0.f);
        }
        *(float4*)(Y + r * NCOL + tx * 4) = o;
    }
}

/* ---------------- Wdiff = W[0:64] - W[64:128] ---------------------------- */
__global__ void wdiff_kernel(const float* __restrict__ Wc, float* __restrict__ Wd) {
    int i = blockIdx.x * blockDim.x + threadIdx.x;
    if (i < DD*DD) Wd[i] = Wc[i] - Wc[DD*DD + i];
}

/* ---------------- row sum of squares ------------------------------------- */
__global__ void sq_kernel(const float* __restrict__ ge, float* __restrict__ sq) {
    int r = blockIdx.x * blockDim.x + threadIdx.x;
    if (r >= NN) return;
    const float4* p = (const float4*)(ge + r * DD);
    float s0=0.f,s1=0.f,s2=0.f,s3=0.f;
#pragma unroll
    for (int d4 = 0; d4 < 16; d4++) {
        float4 v = p[d4];
        s0 += v.x*v.x; s1 += v.y*v.y; s2 += v.z*v.z; s3 += v.w*v.w;
    }
    sq[r] = (s0+s1)+(s2+s3);
}

/* ---------------- KNN: top-5 smallest sq-euclid per query ----------------
   32 queries/block, 8 slices (256 threads). db tiled 64 pts in shared.
   Stable tie-break identical to jax.lax.top_k (smaller index first).      */
__global__ __launch_bounds__(256, 2) void knn_kernel(
    const float* __restrict__ ge, const float* __restrict__ sq,
    int* __restrict__ idxflat)
{
    const int bb    = blockIdx.y;
    const int lane  = threadIdx.x & 31;
    const int slice = threadIdx.x >> 5;
    const int j     = blockIdx.x * 32 + lane;     /* query index */
    const float* gb  = ge + bb * NPTS * DD;
    const float* sqb = sq + bb * NPTS;

    float qv[DD];
#pragma unroll
    for (int d4 = 0; d4 < 16; d4++) {
        float4 v = ((const float4*)(gb + j * DD))[d4];
        qv[d4*4+0]=v.x; qv[d4*4+1]=v.y; qv[d4*4+2]=v.z; qv[d4*4+3]=v.w;
    }
    const float sqj = sqb[j];

    float tv[5]; int ti[5];
#pragma unroll
    for (int k = 0; k < 5; k++) { tv[k] = FLT_MAX; ti[k] = 0x7FFFFFFF; }

    __shared__ float xs[64 * DD];
    __shared__ float sqs[64];

    for (int tt = 0; tt < NPTS / 64; tt++) {
        __syncthreads();
        {
            const float4* src = (const float4*)(gb + tt * 64 * DD);
            float4* dstp = (float4*)xs;
            for (int f = threadIdx.x; f < 64 * DD / 4; f += 256) dstp[f] = src[f];
            if (threadIdx.x < 64) sqs[threadIdx.x] = sqb[tt * 64 + threadIdx.x];
        }
        __syncthreads();
#pragma unroll
        for (int p = 0; p < 8; p++) {
            const int il = slice * 8 + p;
            const float4* xp = (const float4*)(xs + il * DD);
            float a0=0.f,a1=0.f,a2=0.f,a3=0.f;
#pragma unroll
            for (int d4 = 0; d4 < 16; d4++) {
                float4 v = xp[d4];
                a0 += qv[d4*4+0]*v.x; a1 += qv[d4*4+1]*v.y;
                a2 += qv[d4*4+2]*v.z; a3 += qv[d4*4+3]*v.w;
            }
            float dot  = (a0+a1)+(a2+a3);
            float dist = fmaxf(sqj + sqs[il] - 2.0f * dot, 0.0f);
            int   i    = tt * 64 + il;
            if (dist < tv[4]) {
                tv[4] = dist; ti[4] = i;
#pragma unroll
                for (int s2 = 4; s2 > 0; s2--) {
                    if (tv[s2] < tv[s2-1]) {
                        float fv = tv[s2]; tv[s2] = tv[s2-1]; tv[s2-1] = fv;
                        int  iv = ti[s2]; ti[s2] = ti[s2-1]; ti[s2-1] = iv;
                    }
                }
            }
        }
    }

    /* merge 8 slices x 5 candidates per query, (val,idx) lexicographic */
    __syncthreads();
    float* mv = xs;
    int*   mi = (int*)(xs + 32 * 40);
#pragma unroll
    for (int k = 0; k < 5; k++) {
        mv[lane * 40 + slice * 5 + k] = tv[k];
        mi[lane * 40 + slice * 5 + k] = ti[k];
    }
    __syncthreads();
    if (slice == 0) {
        float bv[5]; int bi[5];
#pragma unroll
        for (int k = 0; k < 5; k++) { bv[k] = FLT_MAX; bi[k] = 0x7FFFFFFF; }
        for (int e = 0; e < 40; e++) {
            float v = mv[lane * 40 + e];
            int   i = mi[lane * 40 + e];
            if (v < bv[4] || (v == bv[4] && i < bi[4])) {
                bv[4] = v; bi[4] = i;
#pragma unroll
                for (int s2 = 4; s2 > 0; s2--) {
                    if (bv[s2] < bv[s2-1] || (bv[s2] == bv[s2-1] && bi[s2] < bi[s2-1])) {
                        float fv = bv[s2]; bv[s2] = bv[s2-1]; bv[s2-1] = fv;
                        int  iv = bi[s2]; bi[s2] = bi[s2-1]; bi[s2-1] = iv;
                    }
                }
            }
        }
#pragma unroll
        for (int k = 0; k < 5; k++)
            idxflat[bb * NKB + k * NPTS + j] = bi[k];   /* flat[b][k*n+j] */
    }
}

/* ---------------- logprobs: lp[b,i,kk,layer] ----------------------------- */
__global__ void lp_kernel(const float* __restrict__ ge, const int* __restrict__ idxflat,
                          const float* __restrict__ tptr, float* __restrict__ outp, int layer)
{
    int gid = blockIdx.x * blockDim.x + threadIdx.x;
    if (gid >= NB * NKB) return;
    int bb = gid / NKB;
    int m  = gid - bb * NKB;
    float tval = fminf(fmaxf(tptr[0], -5.0f), 5.0f);
    float t = expf(tval);
    int nb  = idxflat[bb * NKB + m];
    int ctr = m / KK;
    int kk  = m - ctr * KK;
    const float4* pa = (const float4*)(ge + (bb * NPTS + nb) * DD);
    const float4* pb = (const float4*)(ge + (bb * NPTS + ctr) * DD);
    float s = 0.f;
#pragma unroll
    for (int d4 = 0; d4 < 16; d4++) {
        float4 a = pa[d4], b4 = pb[d4];
        float dx=a.x-b4.x, dy=a.y-b4.y, dz=a.z-b4.z, dw=a.w-b4.w;
        s += dx*dx + dy*dy + dz*dz + dw*dw;
    }
    outp[((bb * NPTS + ctr) * KK + kk) * 2 + layer] = -s * t;
}

/* ---------------- scatter-max edge conv --------------------------------- */
__global__ void init_acc_kernel(unsigned* __restrict__ acc) {
    int i = blockIdx.x * blockDim.x + threadIdx.x;
    if (i < NN * DD) acc[i] = NEG_MAX_KEY;
}

__global__ void scatter_kernel(const int* __restrict__ idxflat,
                               const float* __restrict__ A, const float* __restrict__ B,
                               unsigned* __restrict__ acc)
{
    int gid = blockIdx.x * blockDim.x + threadIdx.x;
    if (gid >= EDGES * 16) return;
    int q  = gid >> 4;
    int cg = gid & 15;
    /* e = transpose(edges+offset,(1,0,2)).reshape(2,-1) with b=2:
       flat f-index = m*4 + bb*2 + c; e[0]=f in [0,EDGES), e[1]=f in [EDGES,2E). */
    int mq = q >> 2;
    int bb = (q >> 1) & 1;
    int c  = q & 1;
    int m_s = mq;
    int m_d = mq + NKB / 2;
    int srcv = (c == 0) ? idxflat[bb * NKB + m_s] : (m_s / KK);
    int dstv = (c == 0) ? idxflat[bb * NKB + m_d] : (m_d / KK);
    srcv += bb * NPTS;
    dstv += bb * NPTS;
    float4 av = ((const float4*)A)[dstv * 16 + cg];
    float4 bv = ((const float4*)B)[srcv * 16 + cg];
    unsigned* base = acc + dstv * DD + cg * 4;
    atomicMax(base + 0, fkey(av.x + bv.x));
    atomicMax(base + 1, fkey(av.y + bv.y));
    atomicMax(base + 2, fkey(av.z + bv.z));
    atomicMax(base + 3, fkey(av.w + bv.w));
}

__global__ void decode_relu_kernel(const unsigned* __restrict__ acc, float* __restrict__ y) {
    int i = blockIdx.x * blockDim.x + threadIdx.x;
    if (i < NN * DD) y[i] = fmaxf(fdec(acc[i]), 0.0f);
}

/* ---------------- fused head: lrelu(x@Wf1+b)@Wf2+b ----------------------- */
__global__ __launch_bounds__(128) void head_kernel(
    const float* __restrict__ x3,
    const float* __restrict__ Wf1, const float* __restrict__ bf1,
    const float* __restrict__ Wf2, const float* __restrict__ bf2,
    float* __restrict__ out)
{
    __shared__ float w1[64 * 32];
    __shared__ float w2[32 * 8];
    __shared__ float b1s[32], b2s[8];
    int t = threadIdx.x;
    for (int f = t; f < 2048; f += 128) w1[f] = Wf1[f];
    for (int f = t; f < 256;  f += 128) w2[f] = Wf2[f];
    if (t < 32) b1s[t] = bf1[t];
    if (t < 8)  b2s[t] = bf2[t];
    __syncthreads();
    int r = blockIdx.x * 128 + t;
    if (r >= NN) return;
    float xr[64];
#pragma unroll
    for (int d4 = 0; d4 < 16; d4++) {
        float4 v = ((const float4*)(x3 + r * DD))[d4];
        xr[d4*4+0]=v.x; xr[d4*4+1]=v.y; xr[d4*4+2]=v.z; xr[d4*4+3]=v.w;
    }
    float o[8];
#pragma unroll
    for (int k = 0; k < 8; k++) o[k] = b2s[k];
    for (int jj = 0; jj < 32; jj++) {
        float h0=0.f,h1=0.f,h2=0.f,h3=0.f;
#pragma unroll
        for (int k = 0; k < 64; k += 4) {
            h0 += xr[k+0] * w1[(k+0)*32 + jj];
            h1 += xr[k+1] * w1[(k+1)*32 + jj];
            h2 += xr[k+2] * w1[(k+2)*32 + jj];
            h3 += xr[k+3] * w1[(k+3)*32 + jj];
        }
        float h = ((h0+h1)+(h2+h3)) + b1s[jj];
        h = h > 0.f ? h : 0.1f * h;
#pragma unroll
        for (int k = 0; k < 8; k++) o[k] += h * w2[jj*8 + k];
    }
#pragma unroll
    for (int k = 0; k < 8; k++) out[r * 8 + k] = o[k];
}

/* ---------------- launch ------------------------------------------------- */
extern "C" void kernel_launch(void* const* d_in, const int* in_sizes, int n_in,
                              void* d_out, int out_size)
{
    const float* x     = (const float*)d_in[0];
    const float* W_pre = (const float*)d_in[1];
    const float* b_pre = (const float*)d_in[2];
    const float* W_d1  = (const float*)d_in[3];
    const float* b_d1  = (const float*)d_in[4];
    const float* t1    = (const float*)d_in[5];
    const float* W_c1  = (const float*)d_in[6];
    const float* b_c1  = (const float*)d_in[7];
    const float* W_d2  = (const float*)d_in[8];
    const float* b_d2  = (const float*)d_in[9];
    const float* t2    = (const float*)d_in[10];
    const float* W_c2  = (const float*)d_in[11];
    const float* b_c2  = (const float*)d_in[12];
    const float* W_f1  = (const float*)d_in[13];
    const float* b_f1  = (const float*)d_in[14];
    const float* W_f2  = (const float*)d_in[15];
    const float* b_f2  = (const float*)d_in[16];

    float* out = (float*)d_out;            /* [2,4096,8] = 65536 floats   */
    float* lp  = out + NN * 8;             /* [2,4096,5,2] = 81920 floats */

    float *p_xf1, *p_ge1, *p_ge2, *p_sq, *p_A, *p_B, *p_x2, *p_x3, *p_Wdiff;
    int *p_idx1, *p_idx2;
    unsigned *p_acc;
    cudaGetSymbolAddress((void**)&p_xf1,  g_xf1);
    cudaGetSymbolAddress((void**)&p_ge1,  g_ge1);
    cudaGetSymbolAddress((void**)&p_ge2,  g_ge2);
    cudaGetSymbolAddress((void**)&p_sq,   g_sq);
    cudaGetSymbolAddress((void**)&p_idx1, g_idx1);
    cudaGetSymbolAddress((void**)&p_idx2, g_idx2);
    cudaGetSymbolAddress((void**)&p_A,    g_A);
    cudaGetSymbolAddress((void**)&p_B,    g_B);
    cudaGetSymbolAddress((void**)&p_acc,  g_acc);
    cudaGetSymbolAddress((void**)&p_x2,   g_x2);
    cudaGetSymbolAddress((void**)&p_x3,   g_x3);
    cudaGetSymbolAddress((void**)&p_Wdiff,g_Wdiff);

    const float* nul = nullptr;

    /* pre MLP + embed 1 */
    gemm_act<64><<<NN/64, 256>>>(x,     32, nul, 0, W_pre, b_pre, p_xf1, 1);
    gemm_act<64><<<NN/64, 256>>>(p_xf1, 64, nul, 0, W_d1,  b_d1,  p_ge1, 0);

    /* knn 1 + lp 1 */
    sq_kernel<<<NN/256, 256>>>(p_ge1, p_sq);
    knn_kernel<<<dim3(NPTS/32, NB), 256>>>(p_ge1, p_sq, p_idx1);
    lp_kernel<<<(NB*NKB)/256, 256>>>(p_ge1, p_idx1, t1, lp, 0);

    /* edge conv 1 */
    wdiff_kernel<<<(DD*DD)/256, 256>>>(W_c1, p_Wdiff);
    gemm_act<64><<<NN/64, 256>>>(p_xf1, 64, nul, 0, p_Wdiff,      b_c1, p_A, 0);
    gemm_act<64><<<NN/64, 256>>>(p_xf1, 64, nul, 0, W_c1 + DD*DD, nul,  p_B, 0);
    init_acc_kernel<<<(NN*DD)/256, 256>>>(p_acc);
    scatter_kernel<<<(EDGES*16)/256, 256>>>(p_idx1, p_A, p_B, p_acc);
    decode_relu_kernel<<<(NN*DD)/256, 256>>>(p_acc, p_x2);

    /* embed 2 on concat[ge1, x2] */
    gemm_act<64><<<NN/64, 256>>>(p_ge1, 64, p_x2, 64, W_d2, b_d2, p_ge2, 0);

    /* knn 2 + lp 2 */
    sq_kernel<<<NN/256, 256>>>(p_ge2, p_sq);
    knn_kernel<<<dim3(NPTS/32, NB), 256>>>(p_ge2, p_sq, p_idx2);
    lp_kernel<<<(NB*NKB)/256, 256>>>(p_ge2, p_idx2, t2, lp, 1);

    /* edge conv 2 */
    wdiff_kernel<<<(DD*DD)/256, 256>>>(W_c2, p_Wdiff);
    gemm_act<64><<<NN/64, 256>>>(p_x2, 64, nul, 0, p_Wdiff,      b_c2, p_A, 0);
    gemm_act<64><<<NN/64, 256>>>(p_x2, 64, nul, 0, W_c2 + DD*DD, nul,  p_B, 0);
    init_acc_kernel<<<(NN*DD)/256, 256>>>(p_acc);
    scatter_kernel<<<(EDGES*16)/256, 256>>>(p_idx2, p_A, p_B, p_acc);
    decode_relu_kernel<<<(NN*DD)/256, 256>>>(p_acc, p_x3);

    /* head */
    head_kernel<<<NN/128, 128>>>(p_x3, W_f1, b_f1, W_f2, b_f2, out);
}